// round 10
// baseline (speedup 1.0000x reference)
#include <cuda_runtime.h>
#include <cuda_bf16.h>
#include <cstdint>

#define DD 16
#define LL 6
#define KK 64
#define BLOCK 128
#define TILE_M 128

typedef unsigned long long u64;
typedef unsigned int u32;

#define C1_        (-7.2134752044448169f)   /* -5 * log2(e)          */
#define C2SCALE_   (-14.426950408889634f)   /* -10 * log2(e)         */
#define PI_        3.14159265358979323846f
#define HALF_PI_   1.5707963267948966f
#define LN2_TENTH  0.069314718055994531f    /* 0.1 * ln(2)           */
#define CLIP_      0.99999994f              /* fp32(1.0 - 1e-7)      */

// B operand: [384 comps][24 u32] ; row = [mh(8) | ml(8) | mh(8)] bf16-pairs
__device__ u32   g_B[LL * KK][24];
__device__ float g_c2p[LL * KK];   // folded: C2SCALE*alpha + C1*(pi/2)^2
__device__ float g_wv[LL];

__device__ __forceinline__ u32 pack_bf16x2(float a, float b) {
    __nv_bfloat162 h = __floats2bfloat162_rn(a, b);
    return *reinterpret_cast<u32*>(&h);
}

// ------------------------------------------------------------------ prep
__global__ void prep_kernel(const float* __restrict__ mus,
                            const float* __restrict__ alphas,
                            const float* __restrict__ ws) {
    int tid = threadIdx.x;
    if (tid < LL) {
        float w = ws[tid];
        g_wv[tid] = expf(-w * w);
    }
    if (tid >= LL * KK) return;
    int l = tid >> 6;
    int k = tid & 63;
    const float* m = mus + l * DD * KK + k;   // [L, D, K]
    float v[DD];
    float s = 0.f;
#pragma unroll
    for (int d = 0; d < DD; d++) {
        v[d] = m[d * KK];
        s += v[d] * v[d];
    }
    float inv = 1.0f / sqrtf(s);
#pragma unroll
    for (int d = 0; d < DD; d++) v[d] *= inv;
#pragma unroll
    for (int i = 0; i < 8; i++) {
        float a = v[2 * i], b = v[2 * i + 1];
        __nv_bfloat162 hb = __floats2bfloat162_rn(a, b);
        float ra = a - __bfloat162float(hb.x);
        float rb = b - __bfloat162float(hb.y);
        u32 hw = *reinterpret_cast<u32*>(&hb);
        u32 lw = pack_bf16x2(ra, rb);
        g_B[tid][i]      = hw;   // seg0: mh
        g_B[tid][8 + i]  = lw;   // seg1: ml
        g_B[tid][16 + i] = hw;   // seg2: mh
    }
    g_c2p[tid] = C2SCALE_ * alphas[tid] + C1_ * (HALF_PI_ * HALF_PI_);
}

// ---------------------------------------------------------------- helpers
__device__ __forceinline__ float fast_sqrt(float x) {
    float r; asm("sqrt.approx.f32 %0, %1;" : "=f"(r) : "f"(x)); return r;
}
__device__ __forceinline__ float fast_ex2(float x) {
    float r; asm("ex2.approx.f32 %0, %1;" : "=f"(r) : "f"(x)); return r;
}
__device__ __forceinline__ float fast_lg2(float x) {
    float r; asm("lg2.approx.f32 %0, %1;" : "=f"(r) : "f"(x)); return r;
}
__device__ __forceinline__ u64 fma2(u64 a, u64 b, u64 c) {
    u64 d; asm("fma.rn.f32x2 %0, %1, %2, %3;" : "=l"(d) : "l"(a), "l"(b), "l"(c)); return d;
}
__device__ __forceinline__ u64 pack2(float lo, float hi) {
    u64 d; asm("mov.b64 %0, {%1, %2};" : "=l"(d) : "f"(lo), "f"(hi)); return d;
}
__device__ __forceinline__ void unpack2(u64 v, float& lo, float& hi) {
    asm("mov.b64 {%0, %1}, %2;" : "=f"(lo), "=f"(hi) : "l"(v));
}

// m16n8k16 row.col bf16 -> f32 accumulate (plain PTX, valid on compute_103)
__device__ __forceinline__ void mma16816(float& d0, float& d1, float& d2, float& d3,
                                         u32 a0, u32 a1, u32 a2, u32 a3,
                                         u32 b0, u32 b1) {
    asm volatile(
        "mma.sync.aligned.m16n8k16.row.col.f32.bf16.bf16.f32 "
        "{%0,%1,%2,%3}, {%4,%5,%6,%7}, {%8,%9}, {%0,%1,%2,%3};"
        : "+f"(d0), "+f"(d1), "+f"(d2), "+f"(d3)
        : "r"(a0), "r"(a1), "r"(a2), "r"(a3), "r"(b0), "r"(b1));
}

// ------------------------------------------------------------------ main
__global__ __launch_bounds__(BLOCK, 5)
void main_kernel(const float* __restrict__ xs,
                 float* __restrict__ out,
                 int n_total) {
    __shared__ u32    sA[TILE_M][25];   // 12.8 KB: [xh(8)|xh(8)|xl(8)] + pad
    __shared__ float2 sC2[LL * 32];     // 1.5 KB folded c2' pairs
    __shared__ float  sWV[LL];

    const int tid = threadIdx.x;
    {
        const float2* gc = reinterpret_cast<const float2*>(g_c2p);
        for (int i = tid; i < LL * 32; i += BLOCK) sC2[i] = gc[i];
        if (tid < LL) sWV[tid] = g_wv[tid];
    }

    // ---- build A rows: thread tid owns point blockIdx*128 + tid ----
    int n0 = blockIdx.x * TILE_M + tid;
    int n_c = (n0 < n_total) ? n0 : (n_total - 1);
    {
        const float4* xv = reinterpret_cast<const float4*>(xs + (size_t)n_c * DD);
        float4 v0 = xv[0], v1 = xv[1], v2 = xv[2], v3 = xv[3];
        float x[16] = {v0.x, v0.y, v0.z, v0.w, v1.x, v1.y, v1.z, v1.w,
                       v2.x, v2.y, v2.z, v2.w, v3.x, v3.y, v3.z, v3.w};
#pragma unroll
        for (int i = 0; i < 8; i++) {
            float a = x[2 * i], b = x[2 * i + 1];
            __nv_bfloat162 hb = __floats2bfloat162_rn(a, b);
            float ra = a - __bfloat162float(hb.x);
            float rb = b - __bfloat162float(hb.y);
            u32 hw = *reinterpret_cast<u32*>(&hb);
            u32 lw = pack_bf16x2(ra, rb);
            sA[tid][i]      = hw;
            sA[tid][8 + i]  = hw;
            sA[tid][16 + i] = lw;
        }
    }
    __syncthreads();

    const int wid = tid >> 5;
    const int lane = tid & 31;
    const int gid = lane >> 2;   // quad row id 0..7
    const int tig = lane & 3;    // thread-in-group

    // packed acos minimax constants (duplicated lanes)
    const u64 P7 = pack2(-0.0012624911f, -0.0012624911f);
    const u64 P6 = pack2( 0.0066700901f,  0.0066700901f);
    const u64 P5 = pack2(-0.0170881256f, -0.0170881256f);
    const u64 P4 = pack2( 0.0308918810f,  0.0308918810f);
    const u64 P3 = pack2(-0.0501743046f, -0.0501743046f);
    const u64 P2 = pack2( 0.0889789874f,  0.0889789874f);
    const u64 P1 = pack2(-0.2145988016f, -0.2145988016f);
    const u64 P0 = pack2( 1.5707963050f,  1.5707963050f);
    const float Bc = -(C1_) * PI_;

    const u32* Bu = &g_B[0][0];

    float F[4] = {0.f, 0.f, 0.f, 0.f};   // [mt][row gid / gid+8]

#pragma unroll
    for (int mt = 0; mt < 2; mt++) {
        const int r0 = wid * 32 + mt * 16 + gid;
        // A fragments for this 16-row M-tile (persist across layers)
        u32 a[3][4];
#pragma unroll
        for (int kt = 0; kt < 3; kt++) {
            a[kt][0] = sA[r0][8 * kt + tig];
            a[kt][1] = sA[r0 + 8][8 * kt + tig];
            a[kt][2] = sA[r0][8 * kt + tig + 4];
            a[kt][3] = sA[r0 + 8][8 * kt + tig + 4];
        }

#pragma unroll
        for (int l = 0; l < LL; l++) {
            float acc[8][4];
#pragma unroll
            for (int nt = 0; nt < 8; nt++) {
                acc[nt][0] = 0.f; acc[nt][1] = 0.f;
                acc[nt][2] = 0.f; acc[nt][3] = 0.f;
                const u32* brow = Bu + (l * 64 + nt * 8 + gid) * 24;
#pragma unroll
                for (int kt = 0; kt < 3; kt++) {
                    u32 b0 = __ldg(brow + 8 * kt + tig);
                    u32 b1 = __ldg(brow + 8 * kt + tig + 4);
                    mma16816(acc[nt][0], acc[nt][1], acc[nt][2], acc[nt][3],
                             a[kt][0], a[kt][1], a[kt][2], a[kt][3], b0, b1);
                }
            }

            // ---- epilogue (proven R8 packed math) ----
            float sum0 = 0.f, sum1 = 0.f;
            const float2* cb = sC2 + l * 32;
#pragma unroll
            for (int nt = 0; nt < 8; nt++) {
                float2 cc = cb[4 * nt + tig];
#pragma unroll
                for (int rr = 0; rr < 2; rr++) {
                    float dot0 = acc[nt][2 * rr];
                    float dot1 = acc[nt][2 * rr + 1];
                    float a0 = fminf(fabsf(dot0), CLIP_);
                    float a1 = fminf(fabsf(dot1), CLIP_);
                    u64 pa = pack2(a0, a1);
                    u64 p = fma2(P7, pa, P6);
                    p = fma2(p, pa, P5);
                    p = fma2(p, pa, P4);
                    p = fma2(p, pa, P3);
                    p = fma2(p, pa, P2);
                    p = fma2(p, pa, P1);
                    p = fma2(p, pa, P0);
                    float p0, p1;
                    unpack2(p, p0, p1);
                    float dp0 = fast_sqrt(1.0f - a0) * p0;
                    float dp1 = fast_sqrt(1.0f - a1) * p1;
                    float c0 = copysignf(HALF_PI_ - dp0, dot0);
                    float c1 = copysignf(HALF_PI_ - dp1, dot1);
                    float arg0 = fmaf(fmaf(C1_, c0, Bc), c0, cc.x);
                    float arg1 = fmaf(fmaf(C1_, c1, Bc), c1, cc.y);
                    float e = fast_ex2(arg0) + fast_ex2(arg1);
                    if (rr == 0) sum0 += e; else sum1 += e;
                }
            }
            // quad reduction: lanes tig=0..3 hold disjoint column subsets
            sum0 += __shfl_xor_sync(0xFFFFFFFFu, sum0, 1);
            sum0 += __shfl_xor_sync(0xFFFFFFFFu, sum0, 2);
            sum1 += __shfl_xor_sync(0xFFFFFFFFu, sum1, 1);
            sum1 += __shfl_xor_sync(0xFFFFFFFFu, sum1, 2);

            float w = sWV[l];
            float mc0 = LN2_TENTH * fast_lg2(sum0);
            float mc1 = LN2_TENTH * fast_lg2(sum1);
            F[2 * mt]     = fmaf(w, fmaxf(F[2 * mt], 0.f),     (1.0f - w) * mc0);
            F[2 * mt + 1] = fmaf(w, fmaxf(F[2 * mt + 1], 0.f), (1.0f - w) * mc1);
        }
    }

    // ---- store: lane tig==0 of each quad writes its 4 points ----
    if (tig == 0) {
        int base = blockIdx.x * TILE_M + wid * 32;
#pragma unroll
        for (int mt = 0; mt < 2; mt++) {
            int p0 = base + mt * 16 + gid;
            if (p0 < n_total)
                out[p0] = 0.1f * log1pf(fast_ex2(C2SCALE_ * F[2 * mt]));
            int p1 = p0 + 8;
            if (p1 < n_total)
                out[p1] = 0.1f * log1pf(fast_ex2(C2SCALE_ * F[2 * mt + 1]));
        }
    }
}

extern "C" void kernel_launch(void* const* d_in, const int* in_sizes, int n_in,
                              void* d_out, int out_size) {
    const float* xs     = (const float*)d_in[0];
    const float* mus    = (const float*)d_in[1];
    const float* alphas = (const float*)d_in[2];
    const float* ws     = (const float*)d_in[3];
    float* out = (float*)d_out;

    int n_total = in_sizes[0] / DD;

    prep_kernel<<<1, LL * KK>>>(mus, alphas, ws);
    int blocks = (n_total + TILE_M - 1) / TILE_M;
    main_kernel<<<blocks, BLOCK>>>(xs, out, n_total);
}

// round 11
// speedup vs baseline: 4.1637x; 4.1637x over previous
#include <cuda_runtime.h>
#include <cuda_bf16.h>
#include <cstdint>

#define DD 16
#define LL 6
#define KK 64
#define BLOCK 256
#define TILE_M 256

typedef unsigned long long u64;
typedef unsigned int u32;

#define C1_        (-7.2134752044448169f)   /* -5 * log2(e)          */
#define C2SCALE_   (-14.426950408889634f)   /* -10 * log2(e)         */
#define PI_        3.14159265358979323846f
#define HALF_PI_   1.5707963267948966f
#define LN2_TENTH  0.069314718055994531f    /* 0.1 * ln(2)           */
#define CLIP_      0.99999994f              /* fp32(1.0 - 1e-7)      */

// B operand: [384 comps][16 u32]; row = [mh(8) | ml(8)] bf16-pairs
__device__ u32   g_B[LL * KK][16];
__device__ float g_c2p[LL * KK];   // folded: C2SCALE*alpha + C1*(pi/2)^2
__device__ float g_wv[LL];

__device__ __forceinline__ u32 pack_bf16x2(float a, float b) {
    __nv_bfloat162 h = __floats2bfloat162_rn(a, b);
    return *reinterpret_cast<u32*>(&h);
}

// ------------------------------------------------------------------ prep
__global__ void prep_kernel(const float* __restrict__ mus,
                            const float* __restrict__ alphas,
                            const float* __restrict__ ws) {
    int tid = threadIdx.x;
    if (tid < LL) {
        float w = ws[tid];
        g_wv[tid] = expf(-w * w);
    }
    if (tid >= LL * KK) return;
    int l = tid >> 6;
    int k = tid & 63;
    const float* m = mus + l * DD * KK + k;   // [L, D, K]
    float v[DD];
    float s = 0.f;
#pragma unroll
    for (int d = 0; d < DD; d++) {
        v[d] = m[d * KK];
        s += v[d] * v[d];
    }
    float inv = 1.0f / sqrtf(s);
#pragma unroll
    for (int d = 0; d < DD; d++) v[d] *= inv;
#pragma unroll
    for (int i = 0; i < 8; i++) {
        float a = v[2 * i], b = v[2 * i + 1];
        __nv_bfloat162 hb = __floats2bfloat162_rn(a, b);
        float ra = a - __bfloat162float(hb.x);
        float rb = b - __bfloat162float(hb.y);
        g_B[tid][i]     = *reinterpret_cast<u32*>(&hb);  // mh pairs
        g_B[tid][8 + i] = pack_bf16x2(ra, rb);           // ml pairs
    }
    g_c2p[tid] = C2SCALE_ * alphas[tid] + C1_ * (HALF_PI_ * HALF_PI_);
}

// ---------------------------------------------------------------- helpers
__device__ __forceinline__ float fast_sqrt(float x) {
    float r; asm("sqrt.approx.f32 %0, %1;" : "=f"(r) : "f"(x)); return r;
}
__device__ __forceinline__ float fast_ex2(float x) {
    float r; asm("ex2.approx.f32 %0, %1;" : "=f"(r) : "f"(x)); return r;
}
__device__ __forceinline__ float fast_lg2(float x) {
    float r; asm("lg2.approx.f32 %0, %1;" : "=f"(r) : "f"(x)); return r;
}
__device__ __forceinline__ u64 fma2(u64 a, u64 b, u64 c) {
    u64 d; asm("fma.rn.f32x2 %0, %1, %2, %3;" : "=l"(d) : "l"(a), "l"(b), "l"(c)); return d;
}
__device__ __forceinline__ u64 pack2(float lo, float hi) {
    u64 d; asm("mov.b64 %0, {%1, %2};" : "=l"(d) : "f"(lo), "f"(hi)); return d;
}
__device__ __forceinline__ void unpack2(u64 v, float& lo, float& hi) {
    asm("mov.b64 {%0, %1}, %2;" : "=f"(lo), "=f"(hi) : "l"(v));
}

// m16n8k16 row.col bf16 -> f32 accumulate (plain PTX, valid on compute_103)
__device__ __forceinline__ void mma16816(float& d0, float& d1, float& d2, float& d3,
                                         u32 a0, u32 a1, u32 a2, u32 a3,
                                         u32 b0, u32 b1) {
    asm volatile(
        "mma.sync.aligned.m16n8k16.row.col.f32.bf16.bf16.f32 "
        "{%0,%1,%2,%3}, {%4,%5,%6,%7}, {%8,%9}, {%0,%1,%2,%3};"
        : "+f"(d0), "+f"(d1), "+f"(d2), "+f"(d3)
        : "r"(a0), "r"(a1), "r"(a2), "r"(a3), "r"(b0), "r"(b1));
}

// ------------------------------------------------------------------ main
__global__ __launch_bounds__(BLOCK, 3)
void main_kernel(const float* __restrict__ xs,
                 float* __restrict__ out,
                 int n_total) {
    __shared__ u32    sA[TILE_M][17];   // 17.0 KB: [xh(8)|xl(8)] + pad
    __shared__ u32    sB[LL * KK][17];  // 25.5 KB: [mh(8)|ml(8)] + pad
    __shared__ float2 sC2[LL * 32];     // 1.5 KB folded c2' pairs
    __shared__ float  sWV[LL];

    const int tid = threadIdx.x;
    {
        const float2* gc = reinterpret_cast<const float2*>(g_c2p);
        for (int i = tid; i < LL * 32; i += BLOCK) sC2[i] = gc[i];
        if (tid < LL) sWV[tid] = g_wv[tid];
    }

    // ---- copy B table to smem (one-time, uint4 gmem loads) ----
    {
        const uint4* gb = reinterpret_cast<const uint4*>(&g_B[0][0]);
#pragma unroll
        for (int i = tid; i < LL * KK * 4; i += BLOCK) {   // 1536 uint4
            uint4 v = gb[i];
            int row = i >> 2;
            int w = (i & 3) * 4;
            sB[row][w]     = v.x;
            sB[row][w + 1] = v.y;
            sB[row][w + 2] = v.z;
            sB[row][w + 3] = v.w;
        }
    }

    // ---- build A rows: thread tid owns point blockIdx*256 + tid ----
    int n0 = blockIdx.x * TILE_M + tid;
    int n_c = (n0 < n_total) ? n0 : (n_total - 1);
    {
        const float4* xv = reinterpret_cast<const float4*>(xs + (size_t)n_c * DD);
        float4 v0 = xv[0], v1 = xv[1], v2 = xv[2], v3 = xv[3];
        float x[16] = {v0.x, v0.y, v0.z, v0.w, v1.x, v1.y, v1.z, v1.w,
                       v2.x, v2.y, v2.z, v2.w, v3.x, v3.y, v3.z, v3.w};
#pragma unroll
        for (int i = 0; i < 8; i++) {
            float a = x[2 * i], b = x[2 * i + 1];
            __nv_bfloat162 hb = __floats2bfloat162_rn(a, b);
            float ra = a - __bfloat162float(hb.x);
            float rb = b - __bfloat162float(hb.y);
            sA[tid][i]     = *reinterpret_cast<u32*>(&hb);
            sA[tid][8 + i] = pack_bf16x2(ra, rb);
        }
    }
    __syncthreads();

    const int wid = tid >> 5;
    const int lane = tid & 31;
    const int gid = lane >> 2;   // quad row id 0..7
    const int tig = lane & 3;    // thread-in-group

    // A fragments (xh, xl) for both 16-row m-tiles; persist across layers
    u32 ah[2][4], al[2][4];
#pragma unroll
    for (int mt = 0; mt < 2; mt++) {
        int r0 = wid * 32 + mt * 16 + gid;
        ah[mt][0] = sA[r0][tig];
        ah[mt][1] = sA[r0 + 8][tig];
        ah[mt][2] = sA[r0][tig + 4];
        ah[mt][3] = sA[r0 + 8][tig + 4];
        al[mt][0] = sA[r0][8 + tig];
        al[mt][1] = sA[r0 + 8][8 + tig];
        al[mt][2] = sA[r0][8 + tig + 4];
        al[mt][3] = sA[r0 + 8][8 + tig + 4];
    }

    // packed acos minimax constants (duplicated lanes)
    const u64 P7 = pack2(-0.0012624911f, -0.0012624911f);
    const u64 P6 = pack2( 0.0066700901f,  0.0066700901f);
    const u64 P5 = pack2(-0.0170881256f, -0.0170881256f);
    const u64 P4 = pack2( 0.0308918810f,  0.0308918810f);
    const u64 P3 = pack2(-0.0501743046f, -0.0501743046f);
    const u64 P2 = pack2( 0.0889789874f,  0.0889789874f);
    const u64 P1 = pack2(-0.2145988016f, -0.2145988016f);
    const u64 P0 = pack2( 1.5707963050f,  1.5707963050f);
    const float Bc = -(C1_) * PI_;

    float F[4] = {0.f, 0.f, 0.f, 0.f};   // [mt*2 + rr]

#pragma unroll 1
    for (int l = 0; l < LL; l++) {
        float sums[4] = {0.f, 0.f, 0.f, 0.f};   // [mt*2 + rr]
#pragma unroll
        for (int nt = 0; nt < 8; nt++) {
            const int comp = l * 64 + nt * 8 + gid;
            u32 bh0 = sB[comp][tig];
            u32 bh1 = sB[comp][tig + 4];
            u32 bl0 = sB[comp][8 + tig];
            u32 bl1 = sB[comp][8 + tig + 4];
            float2 cc = sC2[l * 32 + 4 * nt + tig];

#pragma unroll
            for (int mt = 0; mt < 2; mt++) {
                float acc0 = 0.f, acc1 = 0.f, acc2 = 0.f, acc3 = 0.f;
                mma16816(acc0, acc1, acc2, acc3,
                         ah[mt][0], ah[mt][1], ah[mt][2], ah[mt][3], bh0, bh1);
                mma16816(acc0, acc1, acc2, acc3,
                         ah[mt][0], ah[mt][1], ah[mt][2], ah[mt][3], bl0, bl1);
                mma16816(acc0, acc1, acc2, acc3,
                         al[mt][0], al[mt][1], al[mt][2], al[mt][3], bh0, bh1);

                // ---- proven packed epilogue on (acc0,acc1), (acc2,acc3) ----
#pragma unroll
                for (int rr = 0; rr < 2; rr++) {
                    float dot0 = (rr == 0) ? acc0 : acc2;
                    float dot1 = (rr == 0) ? acc1 : acc3;
                    float a0 = fminf(fabsf(dot0), CLIP_);
                    float a1 = fminf(fabsf(dot1), CLIP_);
                    u64 pa = pack2(a0, a1);
                    u64 p = fma2(P7, pa, P6);
                    p = fma2(p, pa, P5);
                    p = fma2(p, pa, P4);
                    p = fma2(p, pa, P3);
                    p = fma2(p, pa, P2);
                    p = fma2(p, pa, P1);
                    p = fma2(p, pa, P0);
                    float p0, p1;
                    unpack2(p, p0, p1);
                    float dp0 = fast_sqrt(1.0f - a0) * p0;
                    float dp1 = fast_sqrt(1.0f - a1) * p1;
                    float c0 = copysignf(HALF_PI_ - dp0, dot0);
                    float c1 = copysignf(HALF_PI_ - dp1, dot1);
                    float arg0 = fmaf(fmaf(C1_, c0, Bc), c0, cc.x);
                    float arg1 = fmaf(fmaf(C1_, c1, Bc), c1, cc.y);
                    sums[mt * 2 + rr] += fast_ex2(arg0) + fast_ex2(arg1);
                }
            }
        }

        float w = sWV[l];
#pragma unroll
        for (int j = 0; j < 4; j++) {
            float s = sums[j];
            s += __shfl_xor_sync(0xFFFFFFFFu, s, 1);
            s += __shfl_xor_sync(0xFFFFFFFFu, s, 2);
            float mc = LN2_TENTH * fast_lg2(s);
            F[j] = fmaf(w, fmaxf(F[j], 0.f), (1.0f - w) * mc);
        }
    }

    // ---- store: lane tig==0 of each quad writes its 4 points ----
    if (tig == 0) {
        int base = blockIdx.x * TILE_M + wid * 32;
#pragma unroll
        for (int mt = 0; mt < 2; mt++) {
            int p0 = base + mt * 16 + gid;
            if (p0 < n_total)
                out[p0] = 0.1f * log1pf(fast_ex2(C2SCALE_ * F[mt * 2]));
            int p1 = p0 + 8;
            if (p1 < n_total)
                out[p1] = 0.1f * log1pf(fast_ex2(C2SCALE_ * F[mt * 2 + 1]));
        }
    }
}

extern "C" void kernel_launch(void* const* d_in, const int* in_sizes, int n_in,
                              void* d_out, int out_size) {
    const float* xs     = (const float*)d_in[0];
    const float* mus    = (const float*)d_in[1];
    const float* alphas = (const float*)d_in[2];
    const float* ws     = (const float*)d_in[3];
    float* out = (float*)d_out;

    int n_total = in_sizes[0] / DD;

    prep_kernel<<<1, LL * KK>>>(mus, alphas, ws);
    int blocks = (n_total + TILE_M - 1) / TILE_M;
    main_kernel<<<blocks, BLOCK>>>(xs, out, n_total);
}